// round 1
// baseline (speedup 1.0000x reference)
#include <cuda_runtime.h>

#define FEAT 64
#define HID 32
#define NCLS 10

// Combined weights (computed once per launch by prep_kernel):
//   g_W[k*64 + j], j<32:  (Wz[0]+Wz[1])[k][j]   (z-gate pre-activation)
//                  j>=32: (Wh[0]+Wh[1])[k][j-32] (candidate pre-activation)
__device__ float g_W[FEAT * 64];
__device__ float g_B[64];
__device__ float g_Wl[HID * NCLS];
__device__ float g_bl[NCLS];

__global__ void prep_kernel(const float* __restrict__ Wz, const float* __restrict__ bz,
                            const float* __restrict__ Wh, const float* __restrict__ bh,
                            const float* __restrict__ Wl, const float* __restrict__ bl) {
    int t = threadIdx.x + blockIdx.x * blockDim.x;
    if (t < FEAT * 64) {
        int k = t >> 6;
        int j = t & 63;
        const float* Wsrc = (j < HID) ? Wz : Wh;
        int jj = j & (HID - 1);
        // W shape (2, 96, 32): element [c][k][jj] at c*96*32 + k*32 + jj
        g_W[t] = Wsrc[k * HID + jj] + Wsrc[96 * HID + k * HID + jj];
    }
    if (t < 64)         g_B[t]  = (t < HID) ? bz[t] : bh[t - HID];
    if (t < HID * NCLS) g_Wl[t] = Wl[t];
    if (t < NCLS)       g_bl[t] = bl[t];
}

__global__ __launch_bounds__(128) void recurrent_gcn_kernel(
    const float* __restrict__ x, float* __restrict__ out, int N) {
    __shared__ float4 sW[FEAT][16];      // 64 rows x 64 cols (as float4) = 16 KB
    __shared__ float  sB[64];
    __shared__ float  sWl[HID * NCLS];   // 320 floats
    __shared__ float  sbl[NCLS];

    int tid = threadIdx.x;
    {
        const float4* gw = (const float4*)g_W;
        float4* swf = (float4*)sW;
        for (int i = tid; i < FEAT * 16; i += 128) swf[i] = gw[i];
        if (tid < 64) sB[tid] = g_B[tid];
        for (int i = tid; i < HID * NCLS; i += 128) sWl[i] = g_Wl[i];
        if (tid < NCLS) sbl[tid] = g_bl[tid];
    }
    __syncthreads();

    long long node = (long long)blockIdx.x * 128 + tid;
    if (node >= N) return;

    float acc[64];
#pragma unroll
    for (int j = 0; j < 64; j++) acc[j] = sB[j];

    const float4* xp = (const float4*)(x + (size_t)node * FEAT);
#pragma unroll 4
    for (int k4 = 0; k4 < 16; k4++) {
        float4 xv = xp[k4];
        float xs[4] = {xv.x, xv.y, xv.z, xv.w};
#pragma unroll
        for (int kk = 0; kk < 4; kk++) {
            float xk = xs[kk];
#pragma unroll
            for (int j4 = 0; j4 < 16; j4++) {
                float4 w = sW[k4 * 4 + kk][j4];
                acc[j4 * 4 + 0] += xk * w.x;
                acc[j4 * 4 + 1] += xk * w.y;
                acc[j4 * 4 + 2] += xk * w.z;
                acc[j4 * 4 + 3] += xk * w.w;
            }
        }
    }

    // Epilogue: z = sigmoid(acc[0:32]), ht = tanh(acc[32:64]),
    // h = relu((1-z)*ht), out = h @ Wl + bl
    float h[HID];
#pragma unroll
    for (int j = 0; j < HID; j++) {
        float z  = __fdividef(1.0f, 1.0f + __expf(-acc[j]));
        float e  = __expf(2.0f * acc[HID + j]);     // tanh(a) = 1 - 2/(e^{2a}+1)
        float th = 1.0f - __fdividef(2.0f, e + 1.0f);
        float hv = (1.0f - z) * th;
        h[j] = fmaxf(hv, 0.0f);
    }

    float o[NCLS];
#pragma unroll
    for (int c = 0; c < NCLS; c++) o[c] = sbl[c];
#pragma unroll
    for (int j = 0; j < HID; j++) {
        float r = h[j];
#pragma unroll
        for (int c = 0; c < NCLS; c++) o[c] += r * sWl[j * NCLS + c];
    }

    float2* op = (float2*)(out + (size_t)node * NCLS);
#pragma unroll
    for (int c = 0; c < 5; c++) op[c] = make_float2(o[2 * c], o[2 * c + 1]);
}

extern "C" void kernel_launch(void* const* d_in, const int* in_sizes, int n_in,
                              void* d_out, int out_size) {
    const float* x  = (const float*)d_in[0];
    // d_in[1] = edge_index (int64), d_in[2] = edge_weight: provably unused (K=1 DConv, H0=0)
    const float* Wz = (const float*)d_in[3];
    const float* bz = (const float*)d_in[4];
    const float* Wh = (const float*)d_in[7];
    const float* bh = (const float*)d_in[8];
    const float* Wl = (const float*)d_in[9];
    const float* bl = (const float*)d_in[10];

    int N = in_sizes[0] / FEAT;

    prep_kernel<<<16, 256>>>(Wz, bz, Wh, bh, Wl, bl);
    recurrent_gcn_kernel<<<(N + 127) / 128, 128>>>(x, (float*)d_out, N);
}

// round 4
// speedup vs baseline: 2.9026x; 2.9026x over previous
#include <cuda_runtime.h>
#include <cstdint>

#define FEAT 64
#define HID 32
#define NCLS 10
#define M_TILE 128
#define STRIDE 68   // padded SMEM row stride (floats): bank = (4*row + col) % 32 -> conflict-free frags

// ---------------- prepped parameters in device globals ----------------
__device__ float g_Wt[64 * 64];   // [n][k], tf32-rounded combined (W0+W1); n<32: Wz col n, n>=32: Wh col n-32
__device__ float g_B[64];
__device__ float g_Wl[HID * NCLS];
__device__ float g_bl[NCLS];

__device__ __forceinline__ float to_tf32(float x) {
    uint32_t u;
    asm("cvt.rna.tf32.f32 %0, %1;" : "=r"(u) : "f"(x));
    return __uint_as_float(u);
}

__global__ void prep_kernel(const float* __restrict__ Wz, const float* __restrict__ bz,
                            const float* __restrict__ Wh, const float* __restrict__ bh,
                            const float* __restrict__ Wl, const float* __restrict__ bl) {
    int t = threadIdx.x + blockIdx.x * blockDim.x;
    if (t < 64 * 64) {
        int n = t >> 6, k = t & 63;
        const float* Wsrc = (n < HID) ? Wz : Wh;
        int nn = n & (HID - 1);
        // W shape (2, 96, 32): [c][k][nn] at c*96*32 + k*32 + nn
        g_Wt[t] = to_tf32(Wsrc[k * HID + nn] + Wsrc[96 * HID + k * HID + nn]);
    }
    if (t < 64)         g_B[t]  = (t < HID) ? bz[t] : bh[t - HID];
    if (t < HID * NCLS) g_Wl[t] = Wl[t];
    if (t < NCLS)       g_bl[t] = bl[t];
}

__device__ __forceinline__ void mma_tf32(float c[4], const uint32_t a[4], uint32_t b0, uint32_t b1) {
    asm volatile("mma.sync.aligned.m16n8k8.row.col.f32.tf32.tf32.f32 "
                 "{%0,%1,%2,%3}, {%4,%5,%6,%7}, {%8,%9}, {%0,%1,%2,%3};"
                 : "+f"(c[0]), "+f"(c[1]), "+f"(c[2]), "+f"(c[3])
                 : "r"(a[0]), "r"(a[1]), "r"(a[2]), "r"(a[3]), "r"(b0), "r"(b1));
}

// ---------------- SMEM layout (dynamic) ----------------
static constexpr int SM_X   = 0;                         // 128 x 68 fp32 (34816 B); reused for D after MMA
static constexpr int SM_W   = 34816;                     // 64 x 68 fp32 (17408 B)
static constexpr int SM_SB  = SM_W + 17408;              // 64 f
static constexpr int SM_SWL = SM_SB + 256;               // 320 f
static constexpr int SM_SBL = SM_SWL + 1280;             // 10 f
static constexpr int SM_TOTAL = SM_SBL + 64;

__global__ __launch_bounds__(128) void gcn_mma_kernel(
    const float* __restrict__ x, float* __restrict__ out, int N) {
    extern __shared__ char smem[];
    float* sX  = (float*)(smem + SM_X);
    float* sW  = (float*)(smem + SM_W);
    float* sB  = (float*)(smem + SM_SB);
    float* sWl = (float*)(smem + SM_SWL);
    float* sbl = (float*)(smem + SM_SBL);

    int tid = threadIdx.x;

    // ---- load x tile: 2048 float4, coalesced; tf32-round; zero-fill OOB rows ----
    {
        const float4* xg = (const float4*)x;
        long long base16 = (long long)blockIdx.x * (M_TILE * 16);
        long long lim16 = (long long)N * 16;
#pragma unroll
        for (int it = 0; it < 16; it++) {
            int i = tid + it * 128;             // float4 index within tile
            long long g = base16 + i;
            float4 v = (g < lim16) ? xg[g] : make_float4(0.f, 0.f, 0.f, 0.f);
            v.x = to_tf32(v.x); v.y = to_tf32(v.y); v.z = to_tf32(v.z); v.w = to_tf32(v.w);
            int row = i >> 4, c4 = i & 15;
            *(float4*)(sX + row * STRIDE + c4 * 4) = v;
        }
    }
    // ---- load weight tile: 1024 float4 (already tf32-rounded in prep) ----
    {
        const float4* wg = (const float4*)g_Wt;
#pragma unroll
        for (int it = 0; it < 8; it++) {
            int i = tid + it * 128;
            int n = i >> 4, c4 = i & 15;
            *(float4*)(sW + n * STRIDE + c4 * 4) = wg[i];
        }
    }
    // ---- epilogue constants ----
    if (tid < 64) sB[tid] = g_B[tid];
    for (int i = tid; i < HID * NCLS; i += 128) sWl[i] = g_Wl[i];
    if (tid < NCLS) sbl[tid] = g_bl[tid];
    __syncthreads();

    // ---- warp-tile MMA: each warp computes 32 nodes x 64 outputs ----
    int wid = tid >> 5, lid = tid & 31;
    int g8 = lid >> 2, t4 = lid & 3;           // groupID, thread-in-group
    int mb = wid * 32;

    float c[2][8][4];
#pragma unroll
    for (int mt = 0; mt < 2; mt++)
#pragma unroll
        for (int nt = 0; nt < 8; nt++)
#pragma unroll
            for (int q = 0; q < 4; q++) c[mt][nt][q] = 0.0f;

    const uint32_t* uX = (const uint32_t*)sX;
    const uint32_t* uW = (const uint32_t*)sW;

#pragma unroll
    for (int ks = 0; ks < 8; ks++) {
        int kc = ks * 8;
        uint32_t a[2][4];
#pragma unroll
        for (int mt = 0; mt < 2; mt++) {
            int r0 = mb + mt * 16 + g8;
            a[mt][0] = uX[r0 * STRIDE + kc + t4];
            a[mt][1] = uX[(r0 + 8) * STRIDE + kc + t4];
            a[mt][2] = uX[r0 * STRIDE + kc + t4 + 4];
            a[mt][3] = uX[(r0 + 8) * STRIDE + kc + t4 + 4];
        }
#pragma unroll
        for (int nt = 0; nt < 8; nt++) {
            uint32_t b0 = uW[(nt * 8 + g8) * STRIDE + kc + t4];
            uint32_t b1 = uW[(nt * 8 + g8) * STRIDE + kc + t4 + 4];
            mma_tf32(c[0][nt], a[0], b0, b1);
            mma_tf32(c[1][nt], a[1], b0, b1);
        }
    }

    __syncthreads();   // all frag reads of sX complete before overwriting with D

    // ---- store C fragments to SMEM (D tile, reusing sX region) ----
    float* sD = sX;
#pragma unroll
    for (int mt = 0; mt < 2; mt++) {
        int r0 = mb + mt * 16 + g8;
#pragma unroll
        for (int nt = 0; nt < 8; nt++) {
            int col = nt * 8 + 2 * t4;
            *(float2*)(sD + r0 * STRIDE + col)       = make_float2(c[mt][nt][0], c[mt][nt][1]);
            *(float2*)(sD + (r0 + 8) * STRIDE + col) = make_float2(c[mt][nt][2], c[mt][nt][3]);
        }
    }
    __syncthreads();

    // ---- epilogue: one node per thread ----
    long long node = (long long)blockIdx.x * M_TILE + tid;
    if (node < N) {
        float d[64];
        const float4* dp = (const float4*)(sD + tid * STRIDE);
#pragma unroll
        for (int j4 = 0; j4 < 16; j4++) {
            float4 v = dp[j4];
            d[j4 * 4 + 0] = v.x; d[j4 * 4 + 1] = v.y; d[j4 * 4 + 2] = v.z; d[j4 * 4 + 3] = v.w;
        }
        float o[NCLS];
#pragma unroll
        for (int cc = 0; cc < NCLS; cc++) o[cc] = sbl[cc];
#pragma unroll
        for (int j = 0; j < HID; j++) {
            float az = d[j] + sB[j];
            float ah = d[HID + j] + sB[HID + j];
            float z  = __fdividef(1.0f, 1.0f + __expf(-az));
            float e  = __expf(2.0f * ah);                 // tanh(a) = 1 - 2/(e^{2a}+1)
            float th = 1.0f - __fdividef(2.0f, e + 1.0f);
            float hv = fmaxf((1.0f - z) * th, 0.0f);
#pragma unroll
            for (int cc = 0; cc < NCLS; cc++) o[cc] += hv * sWl[j * NCLS + cc];
        }
        float2* op = (float2*)(out + (size_t)node * NCLS);
#pragma unroll
        for (int cc = 0; cc < 5; cc++) op[cc] = make_float2(o[2 * cc], o[2 * cc + 1]);
    }
}

extern "C" void kernel_launch(void* const* d_in, const int* in_sizes, int n_in,
                              void* d_out, int out_size) {
    const float* x  = (const float*)d_in[0];
    // d_in[1] edge_index / d_in[2] edge_weight: provably unused (K=1 DConv, H0=0)
    const float* Wz = (const float*)d_in[3];
    const float* bz = (const float*)d_in[4];
    const float* Wh = (const float*)d_in[7];
    const float* bh = (const float*)d_in[8];
    const float* Wl = (const float*)d_in[9];
    const float* bl = (const float*)d_in[10];

    int N = in_sizes[0] / FEAT;

    cudaFuncSetAttribute(gcn_mma_kernel, cudaFuncAttributeMaxDynamicSharedMemorySize, SM_TOTAL);

    prep_kernel<<<16, 256>>>(Wz, bz, Wh, bh, Wl, bl);
    int grid = (N + M_TILE - 1) / M_TILE;
    gcn_mma_kernel<<<grid, 128, SM_TOTAL>>>(x, (float*)d_out, N);
}

// round 5
// speedup vs baseline: 3.0225x; 1.0413x over previous
#include <cuda_runtime.h>
#include <cstdint>

#define FEAT 64
#define HID 32
#define NCLS 10
#define M_TILE 128
#define STRIDE 68   // padded SMEM row stride (floats): bank = (4*row + col) % 32 -> conflict-free frags

// ---------------- prepped parameters ----------------
__device__ float g_Wt[64 * 64];     // [n][k] tf32-RNA combined (W0+W1); n<32: Wz col n, else Wh col n-32
__device__ float g_B[64];           // bz ++ bh
__device__ float g_WlT[16 * STRIDE]; // [c][j] = Wl[j][c], tf32-RNA, rows 10..15 zero, stride 68
__device__ float g_bl[NCLS];

__device__ __forceinline__ float to_tf32(float x) {
    uint32_t u;
    asm("cvt.rna.tf32.f32 %0, %1;" : "=r"(u) : "f"(x));
    return __uint_as_float(u);
}

__global__ void prep_kernel(const float* __restrict__ Wz, const float* __restrict__ bz,
                            const float* __restrict__ Wh, const float* __restrict__ bh,
                            const float* __restrict__ Wl, const float* __restrict__ bl) {
    int t = threadIdx.x + blockIdx.x * blockDim.x;
    if (t < 64 * 64) {
        int n = t >> 6, k = t & 63;
        const float* Wsrc = (n < HID) ? Wz : Wh;
        int nn = n & (HID - 1);
        // W shape (2, 96, 32): [c][k][nn] at c*96*32 + k*32 + nn
        g_Wt[t] = to_tf32(Wsrc[k * HID + nn] + Wsrc[96 * HID + k * HID + nn]);
    }
    if (t < 64) g_B[t] = (t < HID) ? bz[t] : bh[t - HID];
    if (t < 16 * STRIDE) {
        int c = t / STRIDE, j = t % STRIDE;
        g_WlT[t] = (c < NCLS && j < HID) ? to_tf32(Wl[j * NCLS + c]) : 0.0f;
    }
    if (t < NCLS) g_bl[t] = bl[t];
}

__device__ __forceinline__ void mma_tf32(float c[4], const uint32_t a[4], uint32_t b0, uint32_t b1) {
    asm volatile("mma.sync.aligned.m16n8k8.row.col.f32.tf32.tf32.f32 "
                 "{%0,%1,%2,%3}, {%4,%5,%6,%7}, {%8,%9}, {%0,%1,%2,%3};"
                 : "+f"(c[0]), "+f"(c[1]), "+f"(c[2]), "+f"(c[3])
                 : "r"(a[0]), "r"(a[1]), "r"(a[2]), "r"(a[3]), "r"(b0), "r"(b1));
}

__device__ __forceinline__ void cp_async16(uint32_t dst_smem, const void* src) {
    asm volatile("cp.async.ca.shared.global [%0], [%1], 16;" :: "r"(dst_smem), "l"(src));
}
__device__ __forceinline__ uint32_t smem_u32(const void* p) {
    uint32_t a;
    asm("{ .reg .u64 t; cvta.to.shared.u64 t, %1; cvt.u32.u64 %0, t; }" : "=r"(a) : "l"(p));
    return a;
}

// ---------------- SMEM layout ----------------
static constexpr int SM_X   = 0;                      // 128 x 68 f (34816 B); reused as hv tile after main MMA
static constexpr int SM_W   = 34816;                  // 64 x 68 f (17408 B)
static constexpr int SM_WLT = 52224;                  // 16 x 68 f (4352 B)
static constexpr int SM_SB  = 56576;                  // 64 f
static constexpr int SM_SBL = 56832;                  // 10 f
static constexpr int SM_TOTAL = 56896;

__global__ __launch_bounds__(128) void gcn_mma_kernel(
    const float* __restrict__ x, float* __restrict__ out, int N) {
    extern __shared__ char smem[];
    float* sX   = (float*)(smem + SM_X);
    float* sB   = (float*)(smem + SM_SB);
    float* sbl  = (float*)(smem + SM_SBL);
    uint32_t u_base = smem_u32(smem);

    int tid = threadIdx.x;

    // ---- async stage x tile (clamp OOB rows to valid data; stores are guarded later) ----
    {
        long long base16 = (long long)blockIdx.x * (M_TILE * 16);
        long long lim16 = (long long)N * 16 - 1;
#pragma unroll
        for (int it = 0; it < 16; it++) {
            int i = tid + it * 128;                  // float4 index in tile
            long long g = base16 + i; if (g > lim16) g = lim16;
            int row = i >> 4, c4 = i & 15;
            cp_async16(u_base + SM_X + (row * STRIDE + c4 * 4) * 4, (const float4*)x + g);
        }
    }
    // ---- async stage W tile ----
#pragma unroll
    for (int it = 0; it < 8; it++) {
        int i = tid + it * 128;
        int n = i >> 4, c4 = i & 15;
        cp_async16(u_base + SM_W + (n * STRIDE + c4 * 4) * 4, g_Wt + n * 64 + c4 * 4);
    }
    // ---- async stage WlT tile (16*68 floats = 272 float4) ----
    for (int i = tid; i < 272; i += 128)
        cp_async16(u_base + SM_WLT + i * 16, (const float4*)g_WlT + i);

    if (tid < 64) sB[tid] = g_B[tid];
    if (tid < NCLS) sbl[tid] = g_bl[tid];

    asm volatile("cp.async.commit_group;" ::: "memory");
    asm volatile("cp.async.wait_group 0;" ::: "memory");
    __syncthreads();

    // ---- main MMA: each warp computes 32 nodes x 64 gate-pre-activations ----
    int wid = tid >> 5, lid = tid & 31;
    int g8 = lid >> 2, t4 = lid & 3;
    int mb = wid * 32;

    float c[2][8][4];
#pragma unroll
    for (int mt = 0; mt < 2; mt++)
#pragma unroll
        for (int nt = 0; nt < 8; nt++)
#pragma unroll
            for (int q = 0; q < 4; q++) c[mt][nt][q] = 0.0f;

    const uint32_t* uX = (const uint32_t*)sX;
    const uint32_t* uW = (const uint32_t*)(smem + SM_W);

#pragma unroll
    for (int ks = 0; ks < 8; ks++) {
        int kc = ks * 8;
        uint32_t a[2][4];
#pragma unroll
        for (int mt = 0; mt < 2; mt++) {
            int r0 = mb + mt * 16 + g8;
            a[mt][0] = uX[r0 * STRIDE + kc + t4];
            a[mt][1] = uX[(r0 + 8) * STRIDE + kc + t4];
            a[mt][2] = uX[r0 * STRIDE + kc + t4 + 4];
            a[mt][3] = uX[(r0 + 8) * STRIDE + kc + t4 + 4];
        }
#pragma unroll
        for (int nt = 0; nt < 8; nt++) {
            uint32_t b0 = uW[(nt * 8 + g8) * STRIDE + kc + t4];
            uint32_t b1 = uW[(nt * 8 + g8) * STRIDE + kc + t4 + 4];
            mma_tf32(c[0][nt], a[0], b0, b1);
            mma_tf32(c[1][nt], a[1], b0, b1);
        }
    }

    __syncthreads();   // all warps done reading sX before hv overwrites it

    // ---- fragment-local activation; store hv (32 cols, tf32-rounded) into sX region ----
    {
        float2 bzv[4], bhv[4];
#pragma unroll
        for (int a2 = 0; a2 < 4; a2++) {
            bzv[a2] = *(float2*)(sB + a2 * 8 + 2 * t4);
            bhv[a2] = *(float2*)(sB + 32 + a2 * 8 + 2 * t4);
        }
        float* sHV = sX;
#pragma unroll
        for (int mt = 0; mt < 2; mt++) {
#pragma unroll
            for (int rh = 0; rh < 2; rh++) {
                int row = mb + mt * 16 + rh * 8 + g8;
#pragma unroll
                for (int a2 = 0; a2 < 4; a2++) {
                    float z0 = c[mt][a2][2 * rh]     + bzv[a2].x;
                    float z1 = c[mt][a2][2 * rh + 1] + bzv[a2].y;
                    float h0 = c[mt][a2 + 4][2 * rh]     + bhv[a2].x;
                    float h1 = c[mt][a2 + 4][2 * rh + 1] + bhv[a2].y;
                    float s0 = __fdividef(1.0f, 1.0f + __expf(-z0));
                    float s1 = __fdividef(1.0f, 1.0f + __expf(-z1));
                    float e0 = __expf(2.0f * h0), e1 = __expf(2.0f * h1);
                    float t0 = 1.0f - __fdividef(2.0f, e0 + 1.0f);
                    float t1 = 1.0f - __fdividef(2.0f, e1 + 1.0f);
                    float v0 = to_tf32(fmaxf((1.0f - s0) * t0, 0.0f));
                    float v1 = to_tf32(fmaxf((1.0f - s1) * t1, 0.0f));
                    *(float2*)(sHV + row * STRIDE + a2 * 8 + 2 * t4) = make_float2(v0, v1);
                }
            }
        }
    }
    __syncwarp();      // hv produced/consumed within the same warp's 32 rows

    // ---- epilogue MMA: out(32x10) = hv(32x32) @ Wl(32x10), WlT padded to 16 rows ----
    float c2[2][2][4];
#pragma unroll
    for (int mt = 0; mt < 2; mt++)
#pragma unroll
        for (int nt = 0; nt < 2; nt++)
#pragma unroll
            for (int q = 0; q < 4; q++) c2[mt][nt][q] = 0.0f;

    const uint32_t* uHV = (const uint32_t*)sX;
    const uint32_t* uWlT = (const uint32_t*)(smem + SM_WLT);
#pragma unroll
    for (int ks = 0; ks < 4; ks++) {
        int kc = ks * 8;
        uint32_t a[2][4];
#pragma unroll
        for (int mt = 0; mt < 2; mt++) {
            int r0 = mb + mt * 16 + g8;
            a[mt][0] = uHV[r0 * STRIDE + kc + t4];
            a[mt][1] = uHV[(r0 + 8) * STRIDE + kc + t4];
            a[mt][2] = uHV[r0 * STRIDE + kc + t4 + 4];
            a[mt][3] = uHV[(r0 + 8) * STRIDE + kc + t4 + 4];
        }
#pragma unroll
        for (int nt = 0; nt < 2; nt++) {
            uint32_t b0 = uWlT[(nt * 8 + g8) * STRIDE + kc + t4];
            uint32_t b1 = uWlT[(nt * 8 + g8) * STRIDE + kc + t4 + 4];
            mma_tf32(c2[0][nt], a[0], b0, b1);
            mma_tf32(c2[1][nt], a[1], b0, b1);
        }
    }

    // ---- store: thread covers cols {2t4, 2t4+1} and (t4==0) {8,9} for 4 rows ----
    {
        float bl0 = sbl[2 * t4], bl1 = sbl[2 * t4 + 1];
        float bl8 = sbl[8], bl9 = sbl[9];
        long long nb = (long long)blockIdx.x * M_TILE;
#pragma unroll
        for (int mt = 0; mt < 2; mt++) {
#pragma unroll
            for (int rh = 0; rh < 2; rh++) {
                int row = mb + mt * 16 + rh * 8 + g8;
                long long node = nb + row;
                if (node < N) {
                    float* op = out + (size_t)node * NCLS;
                    *(float2*)(op + 2 * t4) = make_float2(c2[mt][0][2 * rh] + bl0,
                                                          c2[mt][0][2 * rh + 1] + bl1);
                    if (t4 == 0)
                        *(float2*)(op + 8) = make_float2(c2[mt][1][2 * rh] + bl8,
                                                         c2[mt][1][2 * rh + 1] + bl9);
                }
            }
        }
    }
}

extern "C" void kernel_launch(void* const* d_in, const int* in_sizes, int n_in,
                              void* d_out, int out_size) {
    const float* x  = (const float*)d_in[0];
    // d_in[1] edge_index / d_in[2] edge_weight: provably unused (K=1 DConv, H0=0)
    const float* Wz = (const float*)d_in[3];
    const float* bz = (const float*)d_in[4];
    const float* Wh = (const float*)d_in[7];
    const float* bh = (const float*)d_in[8];
    const float* Wl = (const float*)d_in[9];
    const float* bl = (const float*)d_in[10];

    int N = in_sizes[0] / FEAT;

    cudaFuncSetAttribute(gcn_mma_kernel, cudaFuncAttributeMaxDynamicSharedMemorySize, SM_TOTAL);

    prep_kernel<<<16, 256>>>(Wz, bz, Wh, bh, Wl, bl);
    int grid = (N + M_TILE - 1) / M_TILE;
    gcn_mma_kernel<<<grid, 128, SM_TOTAL>>>(x, (float*)d_out, N);
}

// round 7
// speedup vs baseline: 3.7149x; 1.2291x over previous
#include <cuda_runtime.h>
#include <cstdint>

#define FEAT 64
#define HID 32
#define NCLS 10
#define M_TILE 128
#define STRIDE 68   // padded row stride (floats): frag addresses hit 32 distinct banks
#define GRID_P 296  // persistent grid: 2 CTAs/SM x 148 SMs

// ---------------- prepped parameters ----------------
__device__ float g_Wt[64 * 64];    // [n][k] tf32-RNA combined (W0+W1); n<32: Wz col n, else Wh col n-32
__device__ float g_B[64];          // bz ++ bh
__device__ float g_WlT[16 * 32];   // [c][j] = Wl[j][c], tf32-RNA, rows 10..15 zero
__device__ float g_bl[NCLS];

__device__ __forceinline__ float to_tf32(float x) {
    uint32_t u;
    asm("cvt.rna.tf32.f32 %0, %1;" : "=r"(u) : "f"(x));
    return __uint_as_float(u);
}

__global__ void prep_kernel(const float* __restrict__ Wz, const float* __restrict__ bz,
                            const float* __restrict__ Wh, const float* __restrict__ bh,
                            const float* __restrict__ Wl, const float* __restrict__ bl) {
    int t = threadIdx.x + blockIdx.x * blockDim.x;
    if (t < 64 * 64) {
        int n = t >> 6, k = t & 63;
        const float* Wsrc = (n < HID) ? Wz : Wh;
        int nn = n & (HID - 1);
        // W shape (2, 96, 32): [c][k][nn] at c*96*32 + k*32 + nn
        g_Wt[t] = to_tf32(Wsrc[k * HID + nn] + Wsrc[96 * HID + k * HID + nn]);
    }
    if (t < 64) g_B[t] = (t < HID) ? bz[t] : bh[t - HID];
    if (t < 16 * 32) {
        int c = t >> 5, j = t & 31;
        g_WlT[t] = (c < NCLS) ? to_tf32(Wl[j * NCLS + c]) : 0.0f;
    }
    if (t < NCLS) g_bl[t] = bl[t];
}

__device__ __forceinline__ void mma_tf32(float c[4], const uint32_t a[4], uint32_t b0, uint32_t b1) {
    asm volatile("mma.sync.aligned.m16n8k8.row.col.f32.tf32.tf32.f32 "
                 "{%0,%1,%2,%3}, {%4,%5,%6,%7}, {%8,%9}, {%0,%1,%2,%3};"
                 : "+f"(c[0]), "+f"(c[1]), "+f"(c[2]), "+f"(c[3])
                 : "r"(a[0]), "r"(a[1]), "r"(a[2]), "r"(a[3]), "r"(b0), "r"(b1));
}

__device__ __forceinline__ void cp_async16(uint32_t dst_smem, const void* src) {
    asm volatile("cp.async.ca.shared.global [%0], [%1], 16;" :: "r"(dst_smem), "l"(src));
}
__device__ __forceinline__ uint32_t smem_u32(const void* p) {
    uint32_t a;
    asm("{ .reg .u64 t; cvta.to.shared.u64 t, %1; cvt.u32.u64 %0, t; }" : "=r"(a) : "l"(p));
    return a;
}

// ---------------- SMEM layout ----------------
static constexpr int X_BYTES = M_TILE * STRIDE * 4;     // 34816
static constexpr int SM_X0 = 0;
static constexpr int SM_X1 = X_BYTES;                   // 34816
static constexpr int SM_W  = 2 * X_BYTES;               // 69632 (64 x 68 f)
static constexpr int SM_TOTAL = SM_W + 64 * STRIDE * 4; // 87040

__global__ __launch_bounds__(128) void gcn_mma_kernel(
    const float* __restrict__ x, float* __restrict__ out, int N, int n_tiles) {
    extern __shared__ char smem[];
    uint32_t u_base = smem_u32(smem);

    int tid = threadIdx.x;
    int wid = tid >> 5, lid = tid & 31;
    int g8 = lid >> 2, t4 = lid & 3;
    int mb = wid * 32;

    const long long lim16 = (long long)N * 16 - 1;

    // ---- one-time: stage W tile + first X tile ----
#pragma unroll
    for (int it = 0; it < 8; it++) {
        int i = tid + it * 128;
        int n = i >> 4, c4 = i & 15;
        cp_async16(u_base + SM_W + (n * STRIDE + c4 * 4) * 4, g_Wt + n * 64 + c4 * 4);
    }
    {
        long long base16 = (long long)blockIdx.x * (M_TILE * 16);
#pragma unroll
        for (int it = 0; it < 16; it++) {
            int i = tid + it * 128;
            long long g = base16 + i; if (g > lim16) g = lim16;
            int row = i >> 4, c4 = i & 15;
            cp_async16(u_base + SM_X0 + (row * STRIDE + c4 * 4) * 4, (const float4*)x + g);
        }
    }
    asm volatile("cp.async.commit_group;" ::: "memory");

    // ---- one-time: hoist epi weights + biases into registers ----
    float b2[4][2][2];
#pragma unroll
    for (int ks = 0; ks < 4; ks++)
#pragma unroll
        for (int nt = 0; nt < 2; nt++) {
            b2[ks][nt][0] = g_WlT[(nt * 8 + g8) * 32 + ks * 8 + t4];
            b2[ks][nt][1] = g_WlT[(nt * 8 + g8) * 32 + ks * 8 + t4 + 4];
        }
    float2 bzv[4], bhv[4];
#pragma unroll
    for (int a2 = 0; a2 < 4; a2++) {
        bzv[a2] = make_float2(g_B[a2 * 8 + 2 * t4], g_B[a2 * 8 + 2 * t4 + 1]);
        bhv[a2] = make_float2(g_B[32 + a2 * 8 + 2 * t4], g_B[32 + a2 * 8 + 2 * t4 + 1]);
    }
    float bl0 = g_bl[2 * t4], bl1 = g_bl[2 * t4 + 1];
    float bl8 = g_bl[8], bl9 = g_bl[9];

    asm volatile("cp.async.wait_group 0;" ::: "memory");
    __syncthreads();

    const uint32_t* uW = (const uint32_t*)(smem + SM_W);
    int buf = 0;

    for (int t = blockIdx.x; t < n_tiles; t += GRID_P) {
        // ---- prefetch next tile into the other buffer ----
        int tn = t + GRID_P;
        if (tn < n_tiles) {
            int dst = buf ? SM_X0 : SM_X1;
            long long base16 = (long long)tn * (M_TILE * 16);
#pragma unroll
            for (int it = 0; it < 16; it++) {
                int i = tid + it * 128;
                long long g = base16 + i; if (g > lim16) g = lim16;
                int row = i >> 4, c4 = i & 15;
                cp_async16(u_base + dst + (row * STRIDE + c4 * 4) * 4, (const float4*)x + g);
            }
        }
        asm volatile("cp.async.commit_group;" ::: "memory");

        float* sX = (float*)(smem + (buf ? SM_X1 : SM_X0));
        const uint32_t* uX = (const uint32_t*)sX;

        // ---- main MMA: 32 nodes x 64 gate-pre-activations per warp ----
        float c[2][8][4];
#pragma unroll
        for (int mt = 0; mt < 2; mt++)
#pragma unroll
            for (int nt = 0; nt < 8; nt++)
#pragma unroll
                for (int q = 0; q < 4; q++) c[mt][nt][q] = 0.0f;

#pragma unroll
        for (int ks = 0; ks < 8; ks++) {
            int kc = ks * 8;
            uint32_t a[2][4];
#pragma unroll
            for (int mt = 0; mt < 2; mt++) {
                int r0 = mb + mt * 16 + g8;
                a[mt][0] = uX[r0 * STRIDE + kc + t4];
                a[mt][1] = uX[(r0 + 8) * STRIDE + kc + t4];
                a[mt][2] = uX[r0 * STRIDE + kc + t4 + 4];
                a[mt][3] = uX[(r0 + 8) * STRIDE + kc + t4 + 4];
            }
#pragma unroll
            for (int nt = 0; nt < 8; nt++) {
                uint32_t b0 = uW[(nt * 8 + g8) * STRIDE + kc + t4];
                uint32_t b1 = uW[(nt * 8 + g8) * STRIDE + kc + t4 + 4];
                mma_tf32(c[0][nt], a[0], b0, b1);
                mma_tf32(c[1][nt], a[1], b0, b1);
            }
        }

        __syncwarp();   // hv rows below are warp-private; intra-warp ordering suffices

        // ---- fragment-local activation; hv (tf32) into this warp's rows of sX ----
#pragma unroll
        for (int mt = 0; mt < 2; mt++) {
#pragma unroll
            for (int rh = 0; rh < 2; rh++) {
                int row = mb + mt * 16 + rh * 8 + g8;
#pragma unroll
                for (int a2 = 0; a2 < 4; a2++) {
                    float z0 = c[mt][a2][2 * rh]     + bzv[a2].x;
                    float z1 = c[mt][a2][2 * rh + 1] + bzv[a2].y;
                    float h0 = c[mt][a2 + 4][2 * rh]     + bhv[a2].x;
                    float h1 = c[mt][a2 + 4][2 * rh + 1] + bhv[a2].y;
                    float s0 = __fdividef(1.0f, 1.0f + __expf(-z0));
                    float s1 = __fdividef(1.0f, 1.0f + __expf(-z1));
                    float e0 = __expf(2.0f * h0), e1 = __expf(2.0f * h1);
                    float t0 = 1.0f - __fdividef(2.0f, e0 + 1.0f);
                    float t1 = 1.0f - __fdividef(2.0f, e1 + 1.0f);
                    float v0 = to_tf32(fmaxf((1.0f - s0) * t0, 0.0f));
                    float v1 = to_tf32(fmaxf((1.0f - s1) * t1, 0.0f));
                    *(float2*)(sX + row * STRIDE + a2 * 8 + 2 * t4) = make_float2(v0, v1);
                }
            }
        }
        __syncwarp();

        // ---- epilogue MMA: out(32x10) = hv(32x32) @ Wl ----
        float c2[2][2][4];
#pragma unroll
        for (int mt = 0; mt < 2; mt++)
#pragma unroll
            for (int nt = 0; nt < 2; nt++)
#pragma unroll
                for (int q = 0; q < 4; q++) c2[mt][nt][q] = 0.0f;

#pragma unroll
        for (int ks = 0; ks < 4; ks++) {
            int kc = ks * 8;
            uint32_t a[2][4];
#pragma unroll
            for (int mt = 0; mt < 2; mt++) {
                int r0 = mb + mt * 16 + g8;
                a[mt][0] = uX[r0 * STRIDE + kc + t4];
                a[mt][1] = uX[(r0 + 8) * STRIDE + kc + t4];
                a[mt][2] = uX[r0 * STRIDE + kc + t4 + 4];
                a[mt][3] = uX[(r0 + 8) * STRIDE + kc + t4 + 4];
            }
#pragma unroll
            for (int nt = 0; nt < 2; nt++) {
                mma_tf32(c2[0][nt], a[0], __float_as_uint(b2[ks][nt][0]), __float_as_uint(b2[ks][nt][1]));
                mma_tf32(c2[1][nt], a[1], __float_as_uint(b2[ks][nt][0]), __float_as_uint(b2[ks][nt][1]));
            }
        }

        // ---- store outputs ----
        {
            long long nb = (long long)t * M_TILE;
#pragma unroll
            for (int mt = 0; mt < 2; mt++) {
#pragma unroll
                for (int rh = 0; rh < 2; rh++) {
                    int row = mb + mt * 16 + rh * 8 + g8;
                    long long node = nb + row;
                    if (node < N) {
                        float* op = out + (size_t)node * NCLS;
                        *(float2*)(op + 2 * t4) = make_float2(c2[mt][0][2 * rh] + bl0,
                                                              c2[mt][0][2 * rh + 1] + bl1);
                        if (t4 == 0)
                            *(float2*)(op + 8) = make_float2(c2[mt][1][2 * rh] + bl8,
                                                             c2[mt][1][2 * rh + 1] + bl9);
                    }
                }
            }
        }

        asm volatile("cp.async.wait_group 0;" ::: "memory");
        __syncthreads();
        buf ^= 1;
    }
}

extern "C" void kernel_launch(void* const* d_in, const int* in_sizes, int n_in,
                              void* d_out, int out_size) {
    const float* x  = (const float*)d_in[0];
    // d_in[1] edge_index / d_in[2] edge_weight: provably unused (K=1 DConv, H0=0)
    const float* Wz = (const float*)d_in[3];
    const float* bz = (const float*)d_in[4];
    const float* Wh = (const float*)d_in[7];
    const float* bh = (const float*)d_in[8];
    const float* Wl = (const float*)d_in[9];
    const float* bl = (const float*)d_in[10];

    int N = in_sizes[0] / FEAT;
    int n_tiles = (N + M_TILE - 1) / M_TILE;

    cudaFuncSetAttribute(gcn_mma_kernel, cudaFuncAttributeMaxDynamicSharedMemorySize, SM_TOTAL);

    prep_kernel<<<16, 256>>>(Wz, bz, Wh, bh, Wl, bl);
    int grid = n_tiles < GRID_P ? n_tiles : GRID_P;
    gcn_mma_kernel<<<grid, 128, SM_TOTAL>>>(x, (float*)d_out, N, n_tiles);
}